// round 9
// baseline (speedup 1.0000x reference)
#include <cuda_runtime.h>
#include <math.h>

// Problem constants
#define TN    8192
#define LOGN  13
#define HIDN  64
#define BN    8
#define CINN  32
#define COUTN 32
#define CTOTN 1024   // COUT*CIN
#define NFREQ 4097   // rfft bins
#define FSTR  4104   // padded row stride (complex), mult of 8

// padded smem index for FFT: one float2 of pad every 16
#define PADI(i) ((i) + ((i) >> 4))
#define SBUF 8704

typedef unsigned long long u64;

// ---------------- device scratch ------------------------------------------------
__device__ float2 d_tw[TN];                        // exp(-2*pi*i*k/N)
__device__ float  d_h2t[HIDN * TN];                // h2 transposed: [j][t]
__device__ float2 d_G[HIDN * FSTR];                // rfft(h2)
__device__ float2 d_Xf[(size_t)(BN * CINN) * FSTR];   // rfft(x)
__device__ float2 d_Yf[(size_t)(BN * COUTN) * FSTR];  // result spectra (half)

// ---------------- complex helpers -----------------------------------------------
__device__ __forceinline__ float2 cadd(float2 a, float2 b) { return make_float2(a.x + b.x, a.y + b.y); }
__device__ __forceinline__ float2 csub(float2 a, float2 b) { return make_float2(a.x - b.x, a.y - b.y); }
__device__ __forceinline__ float2 cmul(float2 a, float2 b) {
    return make_float2(a.x * b.x - a.y * b.y, a.x * b.y + a.y * b.x);
}

// ---------------- twiddle table -------------------------------------------------
__global__ void k_twiddle() {
    int k = blockIdx.x * blockDim.x + threadIdx.x;
    if (k < TN) {
        float s, c;
        sincospif(-2.0f * (float)k / (float)TN, &s, &c);
        d_tw[k] = make_float2(c, s);
    }
}

// ---------------- MLP -----------------------------------------------------------
__global__ void k_mlp(const float* __restrict__ w1, const float* __restrict__ b1,
                      const float* __restrict__ w2, const float* __restrict__ b2) {
    __shared__ float h1[4][HIDN];
    int g = threadIdx.x >> 6;
    int j = threadIdx.x & 63;
    int t = blockIdx.x * 4 + g;
    float pos = (float)t * (1.0f / (float)(TN - 1));
    float z = pos * w1[j] + b1[j];
    h1[g][j] = 0.5f * z * (1.0f + erff(z * 0.7071067811865476f));
    __syncthreads();
    float acc = b2[j];
#pragma unroll
    for (int k = 0; k < HIDN; k++) acc += h1[g][k] * w2[k * HIDN + j];
    float h2 = 0.5f * acc * (1.0f + erff(acc * 0.7071067811865476f));
    d_h2t[j * TN + t] = h2;
}

// ---------------- radix-8 Stockham FFT (8192 pts, 1024 threads) -----------------
__device__ __forceinline__ void dft8(const float2* v, float2* y) {
    const float S = 0.70710678118654752f;
    float2 a0 = cadd(v[0], v[4]), b0 = csub(v[0], v[4]);
    float2 a1 = cadd(v[1], v[5]), b1 = csub(v[1], v[5]);
    float2 a2 = cadd(v[2], v[6]), b2 = csub(v[2], v[6]);
    float2 a3 = cadd(v[3], v[7]), b3 = csub(v[3], v[7]);
    float2 c0 = cadd(a0, a2), c1 = csub(a0, a2);
    float2 c2 = cadd(a1, a3), c3 = csub(a1, a3);
    y[0] = cadd(c0, c2); y[4] = csub(c0, c2);
    float2 mc3 = make_float2(c3.y, -c3.x);
    y[2] = cadd(c1, mc3); y[6] = csub(c1, mc3);
    b1 = make_float2(S * (b1.x + b1.y), S * (b1.y - b1.x));
    b2 = make_float2(b2.y, -b2.x);
    b3 = make_float2(S * (b3.y - b3.x), -S * (b3.x + b3.y));
    float2 d0 = cadd(b0, b2), d1 = csub(b0, b2);
    float2 d2 = cadd(b1, b3), d3 = csub(b1, b3);
    y[1] = cadd(d0, d2); y[5] = csub(d0, d2);
    float2 md3 = make_float2(d3.y, -d3.x);
    y[3] = cadd(d1, md3); y[7] = csub(d1, md3);
}

template <int LS>
__device__ __forceinline__ void pass8(const float2* __restrict__ in,
                                      float2* __restrict__ out, int t) {
    int i = t;
    int j = i & (LS - 1);
    int base = ((i & ~(LS - 1)) << 3) | j;
    float2 v[8], y[8];
#pragma unroll
    for (int q = 0; q < 8; q++) v[q] = in[PADI(i + q * 1024)];
    if (LS > 1) {
#pragma unroll
        for (int q = 1; q < 8; q++)
            v[q] = cmul(v[q], d_tw[j * q * (1024 / LS)]);
    }
    dft8(v, y);
#pragma unroll
    for (int q = 0; q < 8; q++) out[PADI(base + q * LS)] = y[q];
}

__device__ __forceinline__ void fft_passes(float2* A, float2* B, int t) {
    pass8<1>(A, B, t);   __syncthreads();
    pass8<8>(B, A, t);   __syncthreads();
    pass8<64>(A, B, t);  __syncthreads();
    pass8<512>(B, A, t); __syncthreads();
#pragma unroll
    for (int u = 0; u < 4; u++) {
        int i = t + u * 1024;
        float2 a = A[PADI(i)];
        float2 b = cmul(A[PADI(i + 4096)], d_tw[i]);
        B[PADI(i)]        = cadd(a, b);
        B[PADI(i + 4096)] = csub(a, b);
    }
    __syncthreads();
}

// ---------------- forward FFTs: G rows (blocks 0..31) + x rows (32..159) --------
__global__ void __launch_bounds__(1024, 1)
k_fft_fwd(const float* __restrict__ x) {
    extern __shared__ float2 sm[];
    float2* A = sm;
    float2* B = sm + SBUF;
    int t = threadIdx.x;
    const float* ra;
    float2* oa;
    if (blockIdx.x < HIDN / 2) {
        ra = d_h2t + (size_t)(2 * blockIdx.x) * TN;
        oa = d_G   + (size_t)(2 * blockIdx.x) * FSTR;
    } else {
        int bb = blockIdx.x - HIDN / 2;
        ra = x    + (size_t)(2 * bb) * TN;
        oa = d_Xf + (size_t)(2 * bb) * FSTR;
    }
    const float* rb = ra + TN;
#pragma unroll
    for (int u = 0; u < 8; u++) {
        int idx = t + u * 1024;
        A[PADI(idx)] = make_float2(ra[idx], rb[idx]);
    }
    __syncthreads();
    fft_passes(A, B, t);
#pragma unroll
    for (int u = 0; u < 4; u++) {
        int f = t + u * 1024;
        float2 uu = B[PADI(f)];
        float2 vv = B[PADI((TN - f) & (TN - 1))];
        float vx = vv.x, vy = -vv.y;
        oa[f] = make_float2(0.5f * (uu.x + vx), 0.5f * (uu.y + vy));
        float wx = uu.x - vx, wyv = uu.y - vy;
        oa[FSTR + f] = make_float2(0.5f * wyv, -0.5f * wx);
    }
    if (t == 0) {
        float2 uu = B[PADI(TN / 2)];
        oa[TN / 2]        = make_float2(uu.x, 0.f);
        oa[FSTR + TN / 2] = make_float2(uu.y, 0.f);
    }
}

// ---------------- fused filter-GEMM + contraction (packed f32x2 everywhere) -----
// Per block: 2 tiles of 8 freqs (grid 257 = single wave).
// Smem layout (bytes):
//   Gs   : u64[64*8*2]          8192   pre-duplicated {g,g} pairs
//   Ms   : u64[1024*9]          73728  packed f-pairs: row = c-swizzled, 8 slots + pad
//   XsRe : float[32*98]         12544  b-substride 12, i-stride 98
//   XsIm : float[32*98]         12544  stores NEGATED imag
#define MSTR   9     // Ms row stride in u64
#define XBSTR  12    // Xs b substride (floats)
#define XISTR  98    // Xs i stride (floats)
#define OFF_GS   0
#define OFF_MS   (8192 / 8)               // in u64 units
#define OFF_XRE  (8192 + 73728)           // bytes
#define OFF_XIM  (8192 + 73728 + 12544)
#define FUSED_SM (8192 + 73728 + 2 * 12544)

__global__ void __launch_bounds__(256)
k_fused(const float* __restrict__ w3, const float* __restrict__ b3) {
    extern __shared__ __align__(16) char smraw[];
    u64*    Gs   = (u64*)smraw;
    u64*    Msu  = (u64*)smraw + OFF_MS;
    float2* Msf2 = (float2*)Msu;
    float*  XsRe = (float*)(smraw + OFF_XRE);
    float*  XsIm = (float*)(smraw + OFF_XIM);
    int tid = threadIdx.x;

#pragma unroll 1
    for (int tile = 0; tile < 2; tile++) {
        int f0 = (blockIdx.x * 2 + tile) * 8;
        if (f0 >= NFREQ) break;
        int nf = NFREQ - f0; if (nf > 8) nf = 8;

        // ---- stage G (duplicated) ----
        for (int m = tid; m < HIDN * 8; m += 256) {
            int j = m >> 3, f = m & 7;
            float2 g = (f < nf) ? d_G[(size_t)j * FSTR + f0 + f] : make_float2(0.f, 0.f);
            u64 gx, gy;
            asm("mov.b64 %0, {%1, %1};" : "=l"(gx) : "f"(g.x));
            asm("mov.b64 %0, {%1, %1};" : "=l"(gy) : "f"(g.y));
            Gs[m * 2 + 0] = gx;
            Gs[m * 2 + 1] = gy;
        }
        // ---- stage X (SoA, imag negated) ----
        {
            int b = tid >> 5, i = tid & 31;
            const float2* xr = d_Xf + (size_t)tid * FSTR + f0;
            float* pr = XsRe + i * XISTR + b * XBSTR;
            float* pi = XsIm + i * XISTR + b * XBSTR;
#pragma unroll
            for (int f = 0; f < 8; f++) {
                float2 v = (f < nf) ? xr[f] : make_float2(0.f, 0.f);
                pr[f] = v.x;
                pi[f] = -v.y;
            }
        }
        __syncthreads();

        // ---- phase 1: M[c][f] = sum_j w3[j][c] * G[j][f] ----
        {
            int tm = tid >> 2;          // 0..63 : 16-c block
            int tf = tid & 3;           // 0..3  : f-pair
            u64 accR[8][2], accI[8][2];
#pragma unroll
            for (int p = 0; p < 8; p++) {
                accR[p][0] = accR[p][1] = 0ull;
                accI[p][0] = accI[p][1] = 0ull;
            }
            const float* wp = w3 + tm * 16;
            const u64* gbase = Gs + tf * 4;   // (j*8 + 2tf)*2
#pragma unroll 2
            for (int j = 0; j < HIDN; j++) {
                // packed g for the two f-slots (pre-duplicated)
                ulonglong2 g0 = *(const ulonglong2*)(gbase + j * 16);      // {gx0, gy0}
                ulonglong2 g1 = *(const ulonglong2*)(gbase + j * 16 + 2);  // {gx1, gy1}
                // 16 w floats = 8 packed c-pairs, straight from memory
                const ulonglong2* w4 = (const ulonglong2*)(wp + (size_t)j * CTOTN);
#pragma unroll
                for (int q = 0; q < 4; q++) {
                    ulonglong2 wv = w4[q];
                    asm("fma.rn.f32x2 %0, %1, %2, %0;" : "+l"(accR[2*q  ][0]) : "l"(wv.x), "l"(g0.x));
                    asm("fma.rn.f32x2 %0, %1, %2, %0;" : "+l"(accI[2*q  ][0]) : "l"(wv.x), "l"(g0.y));
                    asm("fma.rn.f32x2 %0, %1, %2, %0;" : "+l"(accR[2*q  ][1]) : "l"(wv.x), "l"(g1.x));
                    asm("fma.rn.f32x2 %0, %1, %2, %0;" : "+l"(accI[2*q  ][1]) : "l"(wv.x), "l"(g1.y));
                    asm("fma.rn.f32x2 %0, %1, %2, %0;" : "+l"(accR[2*q+1][0]) : "l"(wv.y), "l"(g0.x));
                    asm("fma.rn.f32x2 %0, %1, %2, %0;" : "+l"(accI[2*q+1][0]) : "l"(wv.y), "l"(g0.y));
                    asm("fma.rn.f32x2 %0, %1, %2, %0;" : "+l"(accR[2*q+1][1]) : "l"(wv.y), "l"(g1.x));
                    asm("fma.rn.f32x2 %0, %1, %2, %0;" : "+l"(accI[2*q+1][1]) : "l"(wv.y), "l"(g1.y));
                }
            }
            // transpose c-pair packing -> f-pair packing, write Ms (swizzled rows)
#pragma unroll
            for (int p = 0; p < 8; p++) {
                float r00, r10, r01, r11, i00, i10, i01, i11;
                asm("mov.b64 {%0, %1}, %2;" : "=f"(r00), "=f"(r10) : "l"(accR[p][0]));
                asm("mov.b64 {%0, %1}, %2;" : "=f"(r01), "=f"(r11) : "l"(accR[p][1]));
                asm("mov.b64 {%0, %1}, %2;" : "=f"(i00), "=f"(i10) : "l"(accI[p][0]));
                asm("mov.b64 {%0, %1}, %2;" : "=f"(i01), "=f"(i11) : "l"(accI[p][1]));
                int c0 = tm * 16 + p * 2;
                if (f0 == 0 && tf == 0) {
                    r00 += (float)TN * b3[c0];
                    r10 += (float)TN * b3[c0 + 1];
                }
                int o0 = c0 >> 5, ii0 = c0 & 31;
                int row0 = o0 * 32 + (ii0 ^ o0);
                int row1 = o0 * 32 + ((ii0 + 1) ^ o0);
                Msf2[row0 * MSTR + 2 * tf]     = make_float2(r00, r01);
                Msf2[row0 * MSTR + 2 * tf + 1] = make_float2(i00, i01);
                Msf2[row1 * MSTR + 2 * tf]     = make_float2(r10, r11);
                Msf2[row1 * MSTR + 2 * tf + 1] = make_float2(i10, i11);
            }
        }
        __syncthreads();

        // ---- phase 2: Y[b][o][f] = sum_i X[b][i][f] * M[o*32+i][f] ----
        {
            int to = tid >> 4;          // 0..15 -> o = 2to+os
            int tb = (tid >> 2) & 3;    // 0..3  -> b = 2tb+bs
            int tf = tid & 3;           // 0..3  -> f-pair
            u64 aR[2][2], aP[2][2], aQ[2][2];   // [os][bs]
#pragma unroll
            for (int a = 0; a < 2; a++)
#pragma unroll
                for (int bq = 0; bq < 2; bq++) {
                    aR[a][bq] = 0ull; aP[a][bq] = 0ull; aQ[a][bq] = 0ull;
                }
#pragma unroll 2
            for (int i = 0; i < CINN; i++) {
                u64 xR[2], xN[2];
#pragma unroll
                for (int bs = 0; bs < 2; bs++) {
                    int boff = i * XISTR + (2 * tb + bs) * XBSTR + 2 * tf;
                    xR[bs] = *(const u64*)(XsRe + boff);
                    xN[bs] = *(const u64*)(XsIm + boff);
                }
                u64 mR[2], mI[2];
#pragma unroll
                for (int os = 0; os < 2; os++) {
                    int o = 2 * to + os;
                    const u64* mp = Msu + (o * 32 + (i ^ o)) * MSTR + 2 * tf;
                    mR[os] = mp[0];
                    mI[os] = mp[1];
                }
#pragma unroll
                for (int os = 0; os < 2; os++)
#pragma unroll
                    for (int bs = 0; bs < 2; bs++) {
                        asm("fma.rn.f32x2 %0, %1, %2, %0;" : "+l"(aR[os][bs]) : "l"(xR[bs]), "l"(mR[os]));
                        asm("fma.rn.f32x2 %0, %1, %2, %0;" : "+l"(aR[os][bs]) : "l"(xN[bs]), "l"(mI[os]));
                        asm("fma.rn.f32x2 %0, %1, %2, %0;" : "+l"(aP[os][bs]) : "l"(xR[bs]), "l"(mI[os]));
                        asm("fma.rn.f32x2 %0, %1, %2, %0;" : "+l"(aQ[os][bs]) : "l"(xN[bs]), "l"(mR[os]));
                    }
            }
#pragma unroll
            for (int os = 0; os < 2; os++)
#pragma unroll
                for (int bs = 0; bs < 2; bs++) {
                    float re0, re1, p0, p1, q0, q1;
                    asm("mov.b64 {%0, %1}, %2;" : "=f"(re0), "=f"(re1) : "l"(aR[os][bs]));
                    asm("mov.b64 {%0, %1}, %2;" : "=f"(p0),  "=f"(p1)  : "l"(aP[os][bs]));
                    asm("mov.b64 {%0, %1}, %2;" : "=f"(q0),  "=f"(q1)  : "l"(aQ[os][bs]));
                    int o = 2 * to + os, b = 2 * tb + bs;
                    float2* yr = d_Yf + (size_t)(b * COUTN + o) * FSTR + f0 + 2 * tf;
                    if (2 * tf < nf)     yr[0] = make_float2(re0, p0 - q0);
                    if (2 * tf + 1 < nf) yr[1] = make_float2(re1, p1 - q1);
                }
        }
        __syncthreads();
    }
}

// ---------------- packed inverse FFT via conj(forward(conj)) --------------------
__global__ void __launch_bounds__(1024, 1)
k_fft_inv(float* __restrict__ out, const float* __restrict__ bias) {
    extern __shared__ float2 sm[];
    float2* A = sm;
    float2* B = sm + SBUF;
    int t = threadIdx.x;
    int b = blockIdx.x >> 4, q = blockIdx.x & 15;
    int oc = 2 * q;
    const float2* ra = d_Yf + (size_t)(b * COUTN + oc) * FSTR;
    const float2* rb = ra + FSTR;
#pragma unroll
    for (int u = 0; u < 4; u++) {
        int f = t + u * 1024;
        float2 Ya = ra[f], Yb = rb[f];
        A[PADI(f)] = make_float2(Ya.x - Yb.y, -(Ya.y + Yb.x));
        if (f > 0)
            A[PADI(TN - f)] = make_float2(Ya.x + Yb.y, Ya.y - Yb.x);
    }
    if (t == 0) {
        float2 Ya = ra[TN / 2], Yb = rb[TN / 2];
        A[PADI(TN / 2)] = make_float2(Ya.x - Yb.y, -(Ya.y + Yb.x));
    }
    __syncthreads();
    fft_passes(A, B, t);
    const float sc = 1.0f / (float)TN;
    float ba = bias[oc], bb = bias[oc + 1];
    float* pa = out + (size_t)(b * COUTN + oc) * TN;
    float* pb = pa + TN;
#pragma unroll
    for (int u = 0; u < 8; u++) {
        int i = t + u * 1024;
        float2 v = B[PADI(i)];
        pa[i] =  v.x * sc + ba;
        pb[i] = -v.y * sc + bb;
    }
}

// ---------------- launch --------------------------------------------------------
extern "C" void kernel_launch(void* const* d_in, const int* in_sizes, int n_in,
                              void* d_out, int out_size) {
    const float* x    = (const float*)d_in[0];
    const float* w1   = (const float*)d_in[1];
    const float* b1   = (const float*)d_in[2];
    const float* w2   = (const float*)d_in[3];
    const float* b2   = (const float*)d_in[4];
    const float* w3   = (const float*)d_in[5];
    const float* b3   = (const float*)d_in[6];
    const float* bias = (const float*)d_in[7];
    float* out = (float*)d_out;

    const int fftSm = 2 * SBUF * (int)sizeof(float2);   // 139264

    cudaFuncSetAttribute(k_fft_fwd, cudaFuncAttributeMaxDynamicSharedMemorySize, fftSm);
    cudaFuncSetAttribute(k_fft_inv, cudaFuncAttributeMaxDynamicSharedMemorySize, fftSm);
    cudaFuncSetAttribute(k_fused,   cudaFuncAttributeMaxDynamicSharedMemorySize, FUSED_SM);

    k_twiddle<<<32, 256>>>();
    k_mlp<<<TN / 4, 256>>>(w1, b1, w2, b2);
    k_fft_fwd<<<HIDN / 2 + BN * CINN / 2, 1024, fftSm>>>(x);
    k_fused<<<257, 256, FUSED_SM>>>(w3, b3);
    k_fft_inv<<<BN * COUTN / 2, 1024, fftSm>>>(out, bias);
}